// round 1
// baseline (speedup 1.0000x reference)
#include <cuda_runtime.h>
#include <cuda_bf16.h>
#include <cstdint>

// ============================================================================
// HyperGRUCell — round 1: correct fp32 baseline
//   Stage 1: 6 batched SGEMMs (4096x1024x1024) -> __device__ scratch
//   Stage 2: fused per-row hyperbolic GRU math  -> d_out
// ============================================================================

#define MDIM 4096
#define NDIM 1024
#define KDIM 1024
#define GSZ  ((size_t)MDIM * NDIM)

// 6 GEMM outputs: [z_inp, z_hid, r_inp, r_hid, h_inp, h_hid]
__device__ float g_scratch[6ull * MDIM * NDIM];

struct WPtrs { const float* w[6]; };

// ----------------------------------------------------------------------------
// SGEMM: C[z] = A[z] @ W[z],  A row-major (M,K), W row-major (K,N)
// BM=BN=128, BK=16, 256 threads, 8x8 per thread, reg-prefetch double buffer
// ----------------------------------------------------------------------------
__global__ void __launch_bounds__(256) sgemm6(const float* __restrict__ inp,
                                              const float* __restrict__ prevh,
                                              WPtrs wp)
{
    constexpr int BM = 128, BN = 128, BK = 16;
    const int gz = blockIdx.z;
    const float* __restrict__ A = (gz & 1) ? prevh : inp;
    const float* __restrict__ B = wp.w[gz];
    float* __restrict__ C = g_scratch + (size_t)gz * GSZ;

    __shared__ float As[BM][BK];   // [m][k]
    __shared__ float Bs[BK][BN];   // [k][n]

    const int tid = threadIdx.x;
    const int tx = tid & 15;       // 0..15 -> n group
    const int ty = tid >> 4;       // 0..15 -> m group
    const int bm = blockIdx.y * BM;
    const int bn = blockIdx.x * BN;

    float4 aPre[2], bPre[2];

#define LOAD_TILE(kt)                                                          \
    do {                                                                       \
        _Pragma("unroll")                                                      \
        for (int i = 0; i < 2; i++) {                                          \
            int idx = tid + i * 256;                                           \
            int ar = idx >> 2, ac = idx & 3;                                   \
            aPre[i] = *reinterpret_cast<const float4*>(                        \
                A + (size_t)(bm + ar) * KDIM + (kt) + ac * 4);                 \
            int br = idx >> 5, bc = idx & 31;                                  \
            bPre[i] = *reinterpret_cast<const float4*>(                        \
                B + (size_t)((kt) + br) * NDIM + bn + bc * 4);                 \
        }                                                                      \
    } while (0)

#define STORE_TILE()                                                           \
    do {                                                                       \
        _Pragma("unroll")                                                      \
        for (int i = 0; i < 2; i++) {                                          \
            int idx = tid + i * 256;                                           \
            int ar = idx >> 2, ac = idx & 3;                                   \
            *reinterpret_cast<float4*>(&As[ar][ac * 4]) = aPre[i];             \
            int br = idx >> 5, bc = idx & 31;                                  \
            *reinterpret_cast<float4*>(&Bs[br][bc * 4]) = bPre[i];             \
        }                                                                      \
    } while (0)

    float acc[8][8];
#pragma unroll
    for (int m = 0; m < 8; m++)
#pragma unroll
        for (int n = 0; n < 8; n++) acc[m][n] = 0.f;

    LOAD_TILE(0);
    STORE_TILE();
    __syncthreads();

    for (int kt = 0; kt < KDIM; kt += BK) {
        const bool has_next = (kt + BK) < KDIM;
        if (has_next) LOAD_TILE(kt + BK);

#pragma unroll
        for (int k = 0; k < BK; k++) {
            float a[8], b[8];
#pragma unroll
            for (int m = 0; m < 8; m++) a[m] = As[ty * 8 + m][k];
#pragma unroll
            for (int n = 0; n < 8; n++) b[n] = Bs[k][tx * 8 + n];
#pragma unroll
            for (int m = 0; m < 8; m++)
#pragma unroll
                for (int n = 0; n < 8; n++)
                    acc[m][n] = fmaf(a[m], b[n], acc[m][n]);
        }
        __syncthreads();
        if (has_next) {
            STORE_TILE();
            __syncthreads();
        }
    }

#pragma unroll
    for (int m = 0; m < 8; m++) {
        const int row = bm + ty * 8 + m;
#pragma unroll
        for (int n = 0; n < 8; n += 4) {
            float4 v = make_float4(acc[m][n], acc[m][n + 1],
                                   acc[m][n + 2], acc[m][n + 3]);
            *reinterpret_cast<float4*>(C + (size_t)row * NDIM + bn + tx * 8 + n) = v;
        }
    }
#undef LOAD_TILE
#undef STORE_TILE
}

// ----------------------------------------------------------------------------
// Fused hyperbolic GRU math: one block per row, 256 threads x 4 elements
// Replicates the reference formulas (clips included) in fp32.
// ----------------------------------------------------------------------------
#define RT 256
#define VPT 4

struct Vec { float v[VPT]; };

__device__ __forceinline__ float artanh_c(float x)
{
    x = fminf(fmaxf(x, -1.f + 1e-5f), 1.f - 1e-5f);
    return 0.5f * (log1pf(x) - log1pf(-x));
}

__device__ __forceinline__ float blockSum1(float v, float* sbuf)
{
    const int lane = threadIdx.x & 31, wid = threadIdx.x >> 5;
#pragma unroll
    for (int o = 16; o; o >>= 1) v += __shfl_xor_sync(0xffffffffu, v, o);
    __syncthreads();
    if (lane == 0) sbuf[wid] = v;
    __syncthreads();
    float s = 0.f;
#pragma unroll
    for (int i = 0; i < 8; i++) s += sbuf[i];
    return s;
}

__device__ __forceinline__ void blockSum2(float a, float b,
                                          float* ra, float* rb, float* sbuf)
{
    const int lane = threadIdx.x & 31, wid = threadIdx.x >> 5;
#pragma unroll
    for (int o = 16; o; o >>= 1) {
        a += __shfl_xor_sync(0xffffffffu, a, o);
        b += __shfl_xor_sync(0xffffffffu, b, o);
    }
    __syncthreads();
    if (lane == 0) { sbuf[wid] = a; sbuf[8 + wid] = b; }
    __syncthreads();
    float sa = 0.f, sb = 0.f;
#pragma unroll
    for (int i = 0; i < 8; i++) { sa += sbuf[i]; sb += sbuf[8 + i]; }
    *ra = sa; *rb = sb;
}

__device__ __forceinline__ void blockSum3(float a, float b, float c,
                                          float* ra, float* rb, float* rc,
                                          float* sbuf)
{
    const int lane = threadIdx.x & 31, wid = threadIdx.x >> 5;
#pragma unroll
    for (int o = 16; o; o >>= 1) {
        a += __shfl_xor_sync(0xffffffffu, a, o);
        b += __shfl_xor_sync(0xffffffffu, b, o);
        c += __shfl_xor_sync(0xffffffffu, c, o);
    }
    __syncthreads();
    if (lane == 0) { sbuf[wid] = a; sbuf[8 + wid] = b; sbuf[16 + wid] = c; }
    __syncthreads();
    float sa = 0.f, sb = 0.f, sc = 0.f;
#pragma unroll
    for (int i = 0; i < 8; i++) {
        sa += sbuf[i]; sb += sbuf[8 + i]; sc += sbuf[16 + i];
    }
    *ra = sa; *rb = sb; *rc = sc;
}

__device__ __forceinline__ void loadVec(Vec& o, const float* p, int tid)
{
#pragma unroll
    for (int j = 0; j < VPT; j++) o.v[j] = p[j * RT + tid];
}

// mobius_matvec tail: m = tanh(||G||/xn * artanh(xn)) * G/||G||
__device__ __forceinline__ void matvecOp(Vec& m, const float* __restrict__ Grow,
                                         float xn, float* sbuf, int tid)
{
    float s = 0.f;
#pragma unroll
    for (int j = 0; j < VPT; j++) {
        float g = Grow[j * RT + tid];
        m.v[j] = g;
        s = fmaf(g, g, s);
    }
    const float g2 = blockSum1(s, sbuf);
    const float gn = sqrtf(fmaxf(g2, 1e-15f));
    const float t = tanhf(gn / xn * artanh_c(xn)) / gn;
#pragma unroll
    for (int j = 0; j < VPT; j++) m.v[j] *= t;
}

// mobius_add(a, b) -> o   (o may alias a or b)
__device__ __forceinline__ void maddOp(Vec& o, const Vec& a, const Vec& b,
                                       float* sbuf)
{
    float sab = 0.f, sa = 0.f, sb = 0.f;
#pragma unroll
    for (int j = 0; j < VPT; j++) {
        sab = fmaf(a.v[j], b.v[j], sab);
        sa  = fmaf(a.v[j], a.v[j], sa);
        sb  = fmaf(b.v[j], b.v[j], sb);
    }
    float ab, a2, b2;
    blockSum3(sab, sa, sb, &ab, &a2, &b2, sbuf);
    const float ca  = 1.f + 2.f * ab + b2;
    const float cb  = 1.f - a2;
    const float den = 1.f + 2.f * ab + a2 * b2;
    const float inv = 1.f / den;
#pragma unroll
    for (int j = 0; j < VPT; j++)
        o.v[j] = (ca * a.v[j] + cb * b.v[j]) * inv;
}

// mobius_pointwise_prod(x, u) -> o   (o may alias x)
__device__ __forceinline__ void pprodOp(Vec& o, const Vec& x, const Vec& u,
                                        float* sbuf)
{
    float ux[VPT];
    float sx = 0.f, su = 0.f;
#pragma unroll
    for (int j = 0; j < VPT; j++) {
        ux[j] = u.v[j] * x.v[j];
        sx = fmaf(x.v[j], x.v[j], sx);
        su = fmaf(ux[j], ux[j], su);
    }
    float x2, ux2;
    blockSum2(sx, su, &x2, &ux2, sbuf);
    const float xn  = sqrtf(fmaxf(x2, 1e-15f));
    const float uxn = sqrtf(fmaxf(ux2, 1e-15f));
    const float t = tanhf(uxn / xn * artanh_c(xn)) / uxn;
#pragma unroll
    for (int j = 0; j < VPT; j++) o.v[j] = t * ux[j];
}

// sigmoid(log0(a)) -> o
__device__ __forceinline__ void siglog0Op(Vec& o, const Vec& a, float* sbuf)
{
    float s = 0.f;
#pragma unroll
    for (int j = 0; j < VPT; j++) s = fmaf(a.v[j], a.v[j], s);
    const float n2 = blockSum1(s, sbuf);
    const float n = sqrtf(fmaxf(n2, 1e-15f));
    const float f = artanh_c(n) / n;
#pragma unroll
    for (int j = 0; j < VPT; j++)
        o.v[j] = 1.f / (1.f + expf(-f * a.v[j]));
}

__global__ void __launch_bounds__(256) hyp_fused(
    const float* __restrict__ inp, const float* __restrict__ prevh,
    const float* __restrict__ bz, const float* __restrict__ br,
    const float* __restrict__ bh, float* __restrict__ out)
{
    __shared__ float sbuf[24];
    const int row = blockIdx.x;
    const int tid = threadIdx.x;
    const size_t off = (size_t)row * NDIM;
    const float* G = g_scratch;

    // norms of inp / prev_h rows; keep prev_h vector
    Vec h;
    float sx = 0.f, sh = 0.f;
#pragma unroll
    for (int j = 0; j < VPT; j++) {
        float xv = inp[off + j * RT + tid];
        h.v[j] = prevh[off + j * RT + tid];
        sx = fmaf(xv, xv, sx);
        sh = fmaf(h.v[j], h.v[j], sh);
    }
    float x2, h2;
    blockSum2(sx, sh, &x2, &h2, sbuf);
    const float xn = sqrtf(fmaxf(x2, 1e-15f));
    const float hn = sqrtf(fmaxf(h2, 1e-15f));

    Vec a, b, bias, z, r;

    // ---- z gate ----
    matvecOp(a, G + 0 * GSZ + off, xn, sbuf, tid);   // mobius_matvec(w_inp_z, inp)
    matvecOp(b, G + 1 * GSZ + off, hn, sbuf, tid);   // mobius_matvec(w_hid_z, prev_h)
    loadVec(bias, bz, tid);
    maddOp(b, b, bias, sbuf);                        // + b_hid_z
    maddOp(a, a, b, sbuf);                           // mobius_add(inp-branch, hid-branch)
    siglog0Op(z, a, sbuf);                           // z = sigmoid(log0(.))

    // ---- r gate ----
    matvecOp(a, G + 2 * GSZ + off, xn, sbuf, tid);
    matvecOp(b, G + 3 * GSZ + off, hn, sbuf, tid);
    loadVec(bias, br, tid);
    maddOp(b, b, bias, sbuf);
    maddOp(a, a, b, sbuf);
    siglog0Op(r, a, sbuf);

    // ---- candidate / update ----
    matvecOp(a, G + 5 * GSZ + off, hn, sbuf, tid);   // mobius_matvec(w_hid_h, prev_h)
    loadVec(bias, bh, tid);
    maddOp(a, a, bias, sbuf);                        // ahh
    pprodOp(a, a, r, sbuf);                          // pointwise_prod(ahh, r)
    matvecOp(b, G + 4 * GSZ + off, xn, sbuf, tid);   // mobius_matvec(w_inp_h, inp)
    maddOp(a, a, b, sbuf);                           // temp_activ
    Vec nh;
#pragma unroll
    for (int j = 0; j < VPT; j++) nh.v[j] = -h.v[j];
    maddOp(a, nh, a, sbuf);                          // minus_h = mobius_add(-prev_h, temp)
    pprodOp(a, a, z, sbuf);                          // pointwise_prod(minus_h, z)
    maddOp(a, h, a, sbuf);                           // h_next = mobius_add(prev_h, .)

#pragma unroll
    for (int j = 0; j < VPT; j++) out[off + j * RT + tid] = a.v[j];
}

// ----------------------------------------------------------------------------
// launch
// ----------------------------------------------------------------------------
extern "C" void kernel_launch(void* const* d_in, const int* in_sizes, int n_in,
                              void* d_out, int out_size)
{
    const float* inp   = (const float*)d_in[0];
    const float* prevh = (const float*)d_in[1];
    WPtrs wp;
    wp.w[0] = (const float*)d_in[2];  // w_inp_z
    wp.w[1] = (const float*)d_in[3];  // w_hid_z
    wp.w[2] = (const float*)d_in[5];  // w_inp_r
    wp.w[3] = (const float*)d_in[6];  // w_hid_r
    wp.w[4] = (const float*)d_in[8];  // w_inp_h
    wp.w[5] = (const float*)d_in[9];  // w_hid_h
    const float* b_z = (const float*)d_in[4];
    const float* b_r = (const float*)d_in[7];
    const float* b_h = (const float*)d_in[10];
    float* out = (float*)d_out;

    dim3 ggrid(NDIM / 128, MDIM / 128, 6);
    sgemm6<<<ggrid, 256>>>(inp, prevh, wp);
    hyp_fused<<<MDIM, 256>>>(inp, prevh, b_z, b_r, b_h, out);
}

// round 3
// speedup vs baseline: 2.5783x; 2.5783x over previous
#include <cuda_runtime.h>
#include <cuda_bf16.h>
#include <cstdint>

// ============================================================================
// HyperGRUCell — round 3: sm80-style mma.sync bf16 3-product GEMM
//   (tcgen05 rejected by ptxas: harness targets plain sm_100, no 'a' features)
//   split_act : fp32 -> bf16 hi/lo for [inp; prev_h]           (K-major)
//   split_wt  : fp32 W[k][n] -> bf16 hi/lo Wt[n][k] (transpose, K-major)
//   gemm6     : C = Ahi@Whi^T + Ahi@Wlo^T + Alo@Whi^T  (fp32 accum, HMMA)
//   hyp_fused : per-row hyperbolic GRU math
// ============================================================================

#define MDIM 4096
#define NDIM 1024
#define KDIM 1024
#define GSZ  ((size_t)MDIM * NDIM)

__device__ float         g_C[6ull * MDIM * NDIM];
__device__ __nv_bfloat16 g_Ahi[8192ull * 1024];
__device__ __nv_bfloat16 g_Alo[8192ull * 1024];
__device__ __nv_bfloat16 g_Whi[6144ull * 1024];
__device__ __nv_bfloat16 g_Wlo[6144ull * 1024];

// ----------------------------------------------------------------------------
// split kernels
// ----------------------------------------------------------------------------
__global__ void __launch_bounds__(256) split_act(const float* __restrict__ inp,
                                                 const float* __restrict__ prevh)
{
    const size_t i = ((size_t)blockIdx.x * 256 + threadIdx.x) * 4;
    const size_t half = (size_t)MDIM * KDIM;
    const float* src = (i < half) ? (inp + i) : (prevh + (i - half));
    float4 v = *reinterpret_cast<const float4*>(src);
    float x[4] = {v.x, v.y, v.z, v.w};
    uint32_t hp[2], lp[2];
#pragma unroll
    for (int j = 0; j < 2; j++) {
        __nv_bfloat16 h0 = __float2bfloat16_rn(x[2 * j]);
        __nv_bfloat16 h1 = __float2bfloat16_rn(x[2 * j + 1]);
        __nv_bfloat16 l0 = __float2bfloat16_rn(x[2 * j] - __bfloat162float(h0));
        __nv_bfloat16 l1 = __float2bfloat16_rn(x[2 * j + 1] - __bfloat162float(h1));
        hp[j] = (uint32_t)__bfloat16_as_ushort(h0) |
                ((uint32_t)__bfloat16_as_ushort(h1) << 16);
        lp[j] = (uint32_t)__bfloat16_as_ushort(l0) |
                ((uint32_t)__bfloat16_as_ushort(l1) << 16);
    }
    *reinterpret_cast<uint2*>(reinterpret_cast<char*>(g_Ahi) + i * 2) = make_uint2(hp[0], hp[1]);
    *reinterpret_cast<uint2*>(reinterpret_cast<char*>(g_Alo) + i * 2) = make_uint2(lp[0], lp[1]);
}

struct WPtrs { const float* w[6]; };

__global__ void __launch_bounds__(256) split_wt(WPtrs wp)
{
    __shared__ float t[32][33];
    const int g = blockIdx.z;
    const float* __restrict__ W = wp.w[g];
    const int tx = threadIdx.x & 31, ty = threadIdx.x >> 5;
    const int n0 = blockIdx.x * 32, k0 = blockIdx.y * 32;
#pragma unroll
    for (int j = 0; j < 4; j++)
        t[ty + j * 8][tx] = W[(size_t)(k0 + ty + j * 8) * NDIM + n0 + tx];
    __syncthreads();
#pragma unroll
    for (int j = 0; j < 4; j++) {
        const float v = t[tx][ty + j * 8];
        __nv_bfloat16 h = __float2bfloat16_rn(v);
        __nv_bfloat16 l = __float2bfloat16_rn(v - __bfloat162float(h));
        const size_t o = (size_t)(g * 1024 + n0 + ty + j * 8) * KDIM + k0 + tx;
        g_Whi[o] = h;
        g_Wlo[o] = l;
    }
}

// ----------------------------------------------------------------------------
// gemm6: BM=BN=128, BK=32, 4 stages, 8 warps (2x4), warp tile 64x32
// ----------------------------------------------------------------------------
#define SSTRIDE 40                      // bf16 elems per smem row (32 data + 8 pad)
#define MAT_ELEMS (128 * SSTRIDE)       // 5120 per matrix per stage
#define STAGE_ELEMS (4 * MAT_ELEMS)     // Ahi, Alo, Whi, Wlo
#define NSTAGE 4
#define SMEM_BYTES (NSTAGE * STAGE_ELEMS * 2)   // 163840

__device__ __forceinline__ void cp16(uint32_t dst, const void* src)
{
    asm volatile("cp.async.cg.shared.global [%0], [%1], 16;"
                 :: "r"(dst), "l"(src) : "memory");
}
#define CP_COMMIT() asm volatile("cp.async.commit_group;" ::: "memory")
#define CP_WAIT(n)  asm volatile("cp.async.wait_group %0;" :: "n"(n) : "memory")

__device__ __forceinline__ void ldsm4(uint32_t* d, uint32_t addr)
{
    asm volatile("ldmatrix.sync.aligned.m8n8.x4.shared.b16 {%0,%1,%2,%3}, [%4];"
                 : "=r"(d[0]), "=r"(d[1]), "=r"(d[2]), "=r"(d[3]) : "r"(addr));
}

__device__ __forceinline__ void mma16816(float* c, const uint32_t* a,
                                         const uint32_t* b)
{
    asm volatile(
        "mma.sync.aligned.m16n8k16.row.col.f32.bf16.bf16.f32 "
        "{%0,%1,%2,%3}, {%4,%5,%6,%7}, {%8,%9}, {%0,%1,%2,%3};"
        : "+f"(c[0]), "+f"(c[1]), "+f"(c[2]), "+f"(c[3])
        : "r"(a[0]), "r"(a[1]), "r"(a[2]), "r"(a[3]), "r"(b[0]), "r"(b[1]));
}

__global__ void __launch_bounds__(256, 1) gemm6()
{
    extern __shared__ __nv_bfloat16 smem[];
    uint32_t sb;
    asm("{ .reg .u64 t; cvta.to.shared.u64 t, %1; cvt.u32.u64 %0, t; }"
        : "=r"(sb) : "l"(smem));

    const int tid  = threadIdx.x;
    const int lane = tid & 31, wid = tid >> 5;
    const int wm = wid >> 2, wn = wid & 3;          // 2 x 4 warps

    const int g  = blockIdx.z;
    const int bm = blockIdx.y * 128;
    const int bn = blockIdx.x * 128;
    const int arow = ((g & 1) << 12) + bm;          // row into [8192] A slab
    const int wrow = (g << 10) + bn;                // row into [6144] W slab

    const __nv_bfloat16* gb[4] = {
        g_Ahi + (size_t)arow * KDIM, g_Alo + (size_t)arow * KDIM,
        g_Whi + (size_t)wrow * KDIM, g_Wlo + (size_t)wrow * KDIM};

    // per-thread load mapping: 8 chunks of 16B
    int l_mat[8], l_row[8], l_ch[8];
#pragma unroll
    for (int i = 0; i < 8; i++) {
        const int idx = tid + i * 256;
        l_mat[i] = idx >> 9;                        // 0..3
        const int wi = idx & 511;
        l_row[i] = wi >> 2;
        l_ch[i]  = wi & 3;
    }

#define LOAD_STAGE(kt, s)                                                      \
    do {                                                                       \
        const uint32_t sbase_ = sb + (uint32_t)(s) * (STAGE_ELEMS * 2);        \
        _Pragma("unroll")                                                      \
        for (int i = 0; i < 8; i++) {                                          \
            const uint32_t dst = sbase_ +                                      \
                (uint32_t)(l_mat[i] * MAT_ELEMS + l_row[i] * SSTRIDE +         \
                           l_ch[i] * 8) * 2;                                   \
            cp16(dst, gb[l_mat[i]] + (size_t)l_row[i] * KDIM +                 \
                      (kt) * 32 + l_ch[i] * 8);                                \
        }                                                                      \
    } while (0)

    float acc[4][4][4];
#pragma unroll
    for (int mt = 0; mt < 4; mt++)
#pragma unroll
        for (int nt = 0; nt < 4; nt++)
#pragma unroll
            for (int j = 0; j < 4; j++) acc[mt][nt][j] = 0.f;

    LOAD_STAGE(0, 0); CP_COMMIT();
    LOAD_STAGE(1, 1); CP_COMMIT();
    LOAD_STAGE(2, 2); CP_COMMIT();

    // ldmatrix lane-derived offsets
    const int a_r = (lane & 7) + ((lane >> 3) & 1) * 8;   // A: row within tile
    const int a_c = (lane >> 4) * 8;                      // A: k offset
    const int b_r = (lane & 7) + (lane >> 4) * 8;         // B: row within 16-n grp
    const int b_c = ((lane >> 3) & 1) * 8;                // B: k offset

    for (int kt = 0; kt < 32; kt++) {
        CP_WAIT(2);
        __syncthreads();
        if (kt + 3 < 32) LOAD_STAGE(kt + 3, (kt + 3) & 3);
        CP_COMMIT();

        const uint32_t sbase = sb + (uint32_t)(kt & 3) * (STAGE_ELEMS * 2);
#pragma unroll
        for (int ks = 0; ks < 2; ks++) {
            uint32_t ah[4][4], al[4][4], bh[4][2], bl[4][2];
#pragma unroll
            for (int mt = 0; mt < 4; mt++) {
                const uint32_t ad = sbase +
                    (uint32_t)((wm * 64 + mt * 16 + a_r) * SSTRIDE +
                               ks * 16 + a_c) * 2;
                ldsm4(ah[mt], ad);
                ldsm4(al[mt], ad + MAT_ELEMS * 2);
            }
#pragma unroll
            for (int p = 0; p < 2; p++) {
                const uint32_t bd = sbase +
                    (uint32_t)(2 * MAT_ELEMS +
                               (wn * 32 + p * 16 + b_r) * SSTRIDE +
                               ks * 16 + b_c) * 2;
                uint32_t q[4];
                ldsm4(q, bd);
                bh[2 * p][0] = q[0]; bh[2 * p][1] = q[1];
                bh[2 * p + 1][0] = q[2]; bh[2 * p + 1][1] = q[3];
                ldsm4(q, bd + MAT_ELEMS * 2);
                bl[2 * p][0] = q[0]; bl[2 * p][1] = q[1];
                bl[2 * p + 1][0] = q[2]; bl[2 * p + 1][1] = q[3];
            }
#pragma unroll
            for (int mt = 0; mt < 4; mt++)
#pragma unroll
                for (int nt = 0; nt < 4; nt++) {
                    mma16816(acc[mt][nt], ah[mt], bh[nt]);
                    mma16816(acc[mt][nt], ah[mt], bl[nt]);
                    mma16816(acc[mt][nt], al[mt], bh[nt]);
                }
        }
    }
    CP_WAIT(0);

    // epilogue: fp32 accumulators -> g_C
    float* Cb = g_C + (size_t)g * GSZ;
    const int mrow = bm + wm * 64 + (lane >> 2);
    const int ncol = bn + wn * 32 + (lane & 3) * 2;
#pragma unroll
    for (int mt = 0; mt < 4; mt++) {
#pragma unroll
        for (int nt = 0; nt < 4; nt++) {
            float* p0 = Cb + (size_t)(mrow + mt * 16) * NDIM + ncol + nt * 8;
            *reinterpret_cast<float2*>(p0) =
                make_float2(acc[mt][nt][0], acc[mt][nt][1]);
            *reinterpret_cast<float2*>(p0 + 8 * NDIM) =
                make_float2(acc[mt][nt][2], acc[mt][nt][3]);
        }
    }
#undef LOAD_STAGE
}

// ----------------------------------------------------------------------------
// Fused hyperbolic GRU math (round-1 proven, 93.5us)
// ----------------------------------------------------------------------------
#define RT 256
#define VPT 4

struct Vec { float v[VPT]; };

__device__ __forceinline__ float artanh_c(float x)
{
    x = fminf(fmaxf(x, -1.f + 1e-5f), 1.f - 1e-5f);
    return 0.5f * (log1pf(x) - log1pf(-x));
}

__device__ __forceinline__ float blockSum1(float v, float* sbuf)
{
    const int lane = threadIdx.x & 31, wid = threadIdx.x >> 5;
#pragma unroll
    for (int o = 16; o; o >>= 1) v += __shfl_xor_sync(0xffffffffu, v, o);
    __syncthreads();
    if (lane == 0) sbuf[wid] = v;
    __syncthreads();
    float s = 0.f;
#pragma unroll
    for (int i = 0; i < 8; i++) s += sbuf[i];
    return s;
}

__device__ __forceinline__ void blockSum2(float a, float b,
                                          float* ra, float* rb, float* sbuf)
{
    const int lane = threadIdx.x & 31, wid = threadIdx.x >> 5;
#pragma unroll
    for (int o = 16; o; o >>= 1) {
        a += __shfl_xor_sync(0xffffffffu, a, o);
        b += __shfl_xor_sync(0xffffffffu, b, o);
    }
    __syncthreads();
    if (lane == 0) { sbuf[wid] = a; sbuf[8 + wid] = b; }
    __syncthreads();
    float sa = 0.f, sb = 0.f;
#pragma unroll
    for (int i = 0; i < 8; i++) { sa += sbuf[i]; sb += sbuf[8 + i]; }
    *ra = sa; *rb = sb;
}

__device__ __forceinline__ void blockSum3(float a, float b, float c,
                                          float* ra, float* rb, float* rc,
                                          float* sbuf)
{
    const int lane = threadIdx.x & 31, wid = threadIdx.x >> 5;
#pragma unroll
    for (int o = 16; o; o >>= 1) {
        a += __shfl_xor_sync(0xffffffffu, a, o);
        b += __shfl_xor_sync(0xffffffffu, b, o);
        c += __shfl_xor_sync(0xffffffffu, c, o);
    }
    __syncthreads();
    if (lane == 0) { sbuf[wid] = a; sbuf[8 + wid] = b; sbuf[16 + wid] = c; }
    __syncthreads();
    float sa = 0.f, sb = 0.f, sc = 0.f;
#pragma unroll
    for (int i = 0; i < 8; i++) {
        sa += sbuf[i]; sb += sbuf[8 + i]; sc += sbuf[16 + i];
    }
    *ra = sa; *rb = sb; *rc = sc;
}

__device__ __forceinline__ void loadVec(Vec& o, const float* p, int tid)
{
#pragma unroll
    for (int j = 0; j < VPT; j++) o.v[j] = p[j * RT + tid];
}

__device__ __forceinline__ void matvecOp(Vec& m, const float* __restrict__ Grow,
                                         float xn, float* sbuf, int tid)
{
    float s = 0.f;
#pragma unroll
    for (int j = 0; j < VPT; j++) {
        float g = Grow[j * RT + tid];
        m.v[j] = g;
        s = fmaf(g, g, s);
    }
    const float g2 = blockSum1(s, sbuf);
    const float gn = sqrtf(fmaxf(g2, 1e-15f));
    const float t = tanhf(gn / xn * artanh_c(xn)) / gn;
#pragma unroll
    for (int j = 0; j < VPT; j++) m.v[j] *= t;
}

__device__ __forceinline__ void maddOp(Vec& o, const Vec& a, const Vec& b,
                                       float* sbuf)
{
    float sab = 0.f, sa = 0.f, sb = 0.f;
#pragma unroll
    for (int j = 0; j < VPT; j++) {
        sab = fmaf(a.v[j], b.v[j], sab);
        sa  = fmaf(a.v[j], a.v[j], sa);
        sb  = fmaf(b.v[j], b.v[j], sb);
    }
    float ab, a2, b2;
    blockSum3(sab, sa, sb, &ab, &a2, &b2, sbuf);
    const float ca  = 1.f + 2.f * ab + b2;
    const float cb  = 1.f - a2;
    const float den = 1.f + 2.f * ab + a2 * b2;
    const float inv = 1.f / den;
#pragma unroll
    for (int j = 0; j < VPT; j++)
        o.v[j] = (ca * a.v[j] + cb * b.v[j]) * inv;
}

__device__ __forceinline__ void pprodOp(Vec& o, const Vec& x, const Vec& u,
                                        float* sbuf)
{
    float ux[VPT];
    float sx = 0.f, su = 0.f;
#pragma unroll
    for (int j = 0; j < VPT; j++) {
        ux[j] = u.v[j] * x.v[j];
        sx = fmaf(x.v[j], x.v[j], sx);
        su = fmaf(ux[j], ux[j], su);
    }
    float x2, ux2;
    blockSum2(sx, su, &x2, &ux2, sbuf);
    const float xn  = sqrtf(fmaxf(x2, 1e-15f));
    const float uxn = sqrtf(fmaxf(ux2, 1e-15f));
    const float t = tanhf(uxn / xn * artanh_c(xn)) / uxn;
#pragma unroll
    for (int j = 0; j < VPT; j++) o.v[j] = t * ux[j];
}

__device__ __forceinline__ void siglog0Op(Vec& o, const Vec& a, float* sbuf)
{
    float s = 0.f;
#pragma unroll
    for (int j = 0; j < VPT; j++) s = fmaf(a.v[j], a.v[j], s);
    const float n2 = blockSum1(s, sbuf);
    const float n = sqrtf(fmaxf(n2, 1e-15f));
    const float f = artanh_c(n) / n;
#pragma unroll
    for (int j = 0; j < VPT; j++)
        o.v[j] = 1.f / (1.f + expf(-f * a.v[j]));
}

__global__ void __launch_bounds__(256) hyp_fused(
    const float* __restrict__ inp, const float* __restrict__ prevh,
    const float* __restrict__ bz, const float* __restrict__ br,
    const float* __restrict__ bh, float* __restrict__ out)
{
    __shared__ float sbuf[24];
    const int row = blockIdx.x;
    const int tid = threadIdx.x;
    const size_t off = (size_t)row * NDIM;
    const float* G = g_C;

    Vec h;
    float sx = 0.f, sh = 0.f;
#pragma unroll
    for (int j = 0; j < VPT; j++) {
        float xv = inp[off + j * RT + tid];
        h.v[j] = prevh[off + j * RT + tid];
        sx = fmaf(xv, xv, sx);
        sh = fmaf(h.v[j], h.v[j], sh);
    }
    float x2, h2;
    blockSum2(sx, sh, &x2, &h2, sbuf);
    const float xn = sqrtf(fmaxf(x2, 1e-15f));
    const float hn = sqrtf(fmaxf(h2, 1e-15f));

    Vec a, b, bias, z, r;

    matvecOp(a, G + 0 * GSZ + off, xn, sbuf, tid);
    matvecOp(b, G + 1 * GSZ + off, hn, sbuf, tid);
    loadVec(bias, bz, tid);
    maddOp(b, b, bias, sbuf);
    maddOp(a, a, b, sbuf);
    siglog0Op(z, a, sbuf);

    matvecOp(a, G + 2 * GSZ + off, xn, sbuf, tid);
    matvecOp(b, G + 3 * GSZ + off, hn, sbuf, tid);
    loadVec(bias, br, tid);
    maddOp(b, b, bias, sbuf);
    maddOp(a, a, b, sbuf);
    siglog0Op(r, a, sbuf);

    matvecOp(a, G + 5 * GSZ + off, hn, sbuf, tid);
    loadVec(bias, bh, tid);
    maddOp(a, a, bias, sbuf);
    pprodOp(a, a, r, sbuf);
    matvecOp(b, G + 4 * GSZ + off, xn, sbuf, tid);
    maddOp(a, a, b, sbuf);
    Vec nh;
#pragma unroll
    for (int j = 0; j < VPT; j++) nh.v[j] = -h.v[j];
    maddOp(a, nh, a, sbuf);
    pprodOp(a, a, z, sbuf);
    maddOp(a, h, a, sbuf);

#pragma unroll
    for (int j = 0; j < VPT; j++) out[off + j * RT + tid] = a.v[j];
}

// ----------------------------------------------------------------------------
// launch
// ----------------------------------------------------------------------------
extern "C" void kernel_launch(void* const* d_in, const int* in_sizes, int n_in,
                              void* d_out, int out_size)
{
    const float* inp   = (const float*)d_in[0];
    const float* prevh = (const float*)d_in[1];
    WPtrs wp;
    wp.w[0] = (const float*)d_in[2];  // w_inp_z
    wp.w[1] = (const float*)d_in[3];  // w_hid_z
    wp.w[2] = (const float*)d_in[5];  // w_inp_r
    wp.w[3] = (const float*)d_in[6];  // w_hid_r
    wp.w[4] = (const float*)d_in[8];  // w_inp_h
    wp.w[5] = (const float*)d_in[9];  // w_hid_h
    const float* b_z = (const float*)d_in[4];
    const float* b_r = (const float*)d_in[7];
    const float* b_h = (const float*)d_in[10];
    float* out = (float*)d_out;

    cudaFuncSetAttribute(gemm6, cudaFuncAttributeMaxDynamicSharedMemorySize,
                         SMEM_BYTES);

    split_act<<<8192, 256>>>(inp, prevh);
    split_wt<<<dim3(32, 32, 6), 256>>>(wp);
    gemm6<<<dim3(8, 32, 6), 256, SMEM_BYTES>>>();
    hyp_fused<<<MDIM, 256>>>(inp, prevh, b_z, b_r, b_h, out);
}

// round 5
// speedup vs baseline: 2.9588x; 1.1476x over previous
#include <cuda_runtime.h>
#include <cuda_bf16.h>
#include <cstdint>

// ============================================================================
// HyperGRUCell — round 5 (= round 4 resubmitted; infra failure last round)
//   split_act : fp32 -> bf16 hi/lo for [inp; prev_h]           (K-major)
//   split_wt  : fp32 W[k][n] -> bf16 hi/lo Wt[n][k] (transpose, K-major)
//   gemm6     : C = Ahi@Whi^T + Ahi@Wlo^T + Alo@Whi^T  (fp32 accum, HMMA)
//               2-stage cp.async pipeline, 2 CTAs/SM
//   hyp_fused : per-row hyperbolic GRU math (rsqrt/__logf/__expf scalar tails)
// ============================================================================

#define MDIM 4096
#define NDIM 1024
#define KDIM 1024
#define GSZ  ((size_t)MDIM * NDIM)

__device__ float         g_C[6ull * MDIM * NDIM];
__device__ __nv_bfloat16 g_Ahi[8192ull * 1024];
__device__ __nv_bfloat16 g_Alo[8192ull * 1024];
__device__ __nv_bfloat16 g_Whi[6144ull * 1024];
__device__ __nv_bfloat16 g_Wlo[6144ull * 1024];

// ----------------------------------------------------------------------------
// split kernels
// ----------------------------------------------------------------------------
__global__ void __launch_bounds__(256) split_act(const float* __restrict__ inp,
                                                 const float* __restrict__ prevh)
{
    const size_t i = ((size_t)blockIdx.x * 256 + threadIdx.x) * 4;
    const size_t half = (size_t)MDIM * KDIM;
    const float* src = (i < half) ? (inp + i) : (prevh + (i - half));
    float4 v = *reinterpret_cast<const float4*>(src);
    float x[4] = {v.x, v.y, v.z, v.w};
    uint32_t hp[2], lp[2];
#pragma unroll
    for (int j = 0; j < 2; j++) {
        __nv_bfloat16 h0 = __float2bfloat16_rn(x[2 * j]);
        __nv_bfloat16 h1 = __float2bfloat16_rn(x[2 * j + 1]);
        __nv_bfloat16 l0 = __float2bfloat16_rn(x[2 * j] - __bfloat162float(h0));
        __nv_bfloat16 l1 = __float2bfloat16_rn(x[2 * j + 1] - __bfloat162float(h1));
        hp[j] = (uint32_t)__bfloat16_as_ushort(h0) |
                ((uint32_t)__bfloat16_as_ushort(h1) << 16);
        lp[j] = (uint32_t)__bfloat16_as_ushort(l0) |
                ((uint32_t)__bfloat16_as_ushort(l1) << 16);
    }
    *reinterpret_cast<uint2*>(reinterpret_cast<char*>(g_Ahi) + i * 2) = make_uint2(hp[0], hp[1]);
    *reinterpret_cast<uint2*>(reinterpret_cast<char*>(g_Alo) + i * 2) = make_uint2(lp[0], lp[1]);
}

struct WPtrs { const float* w[6]; };

__global__ void __launch_bounds__(256) split_wt(WPtrs wp)
{
    __shared__ float t[32][33];
    const int g = blockIdx.z;
    const float* __restrict__ W = wp.w[g];
    const int tx = threadIdx.x & 31, ty = threadIdx.x >> 5;
    const int n0 = blockIdx.x * 32, k0 = blockIdx.y * 32;
#pragma unroll
    for (int j = 0; j < 4; j++)
        t[ty + j * 8][tx] = W[(size_t)(k0 + ty + j * 8) * NDIM + n0 + tx];
    __syncthreads();
#pragma unroll
    for (int j = 0; j < 4; j++) {
        const float v = t[tx][ty + j * 8];
        __nv_bfloat16 h = __float2bfloat16_rn(v);
        __nv_bfloat16 l = __float2bfloat16_rn(v - __bfloat162float(h));
        const size_t o = (size_t)(g * 1024 + n0 + ty + j * 8) * KDIM + k0 + tx;
        g_Whi[o] = h;
        g_Wlo[o] = l;
    }
}

// ----------------------------------------------------------------------------
// gemm6: BM=BN=128, BK=32, 2 stages, 2 CTAs/SM, 8 warps (2x4), warp tile 64x32
// ----------------------------------------------------------------------------
#define SSTRIDE 40                      // bf16 elems per smem row (32 data + 8 pad)
#define MAT_ELEMS (128 * SSTRIDE)       // 5120 per matrix per stage
#define STAGE_ELEMS (4 * MAT_ELEMS)     // Ahi, Alo, Whi, Wlo
#define NSTAGE 2
#define SMEM_BYTES (NSTAGE * STAGE_ELEMS * 2)   // 81920

__device__ __forceinline__ void cp16(uint32_t dst, const void* src)
{
    asm volatile("cp.async.cg.shared.global [%0], [%1], 16;"
                 :: "r"(dst), "l"(src) : "memory");
}
#define CP_COMMIT() asm volatile("cp.async.commit_group;" ::: "memory")
#define CP_WAIT(n)  asm volatile("cp.async.wait_group %0;" :: "n"(n) : "memory")

__device__ __forceinline__ void ldsm4(uint32_t* d, uint32_t addr)
{
    asm volatile("ldmatrix.sync.aligned.m8n8.x4.shared.b16 {%0,%1,%2,%3}, [%4];"
                 : "=r"(d[0]), "=r"(d[1]), "=r"(d[2]), "=r"(d[3]) : "r"(addr));
}

__device__ __forceinline__ void mma16816(float* c, const uint32_t* a,
                                         const uint32_t* b)
{
    asm volatile(
        "mma.sync.aligned.m16n8k16.row.col.f32.bf16.bf16.f32 "
        "{%0,%1,%2,%3}, {%4,%5,%6,%7}, {%8,%9}, {%0,%1,%2,%3};"
        : "+f"(c[0]), "+f"(c[1]), "+f"(c[2]), "+f"(c[3])
        : "r"(a[0]), "r"(a[1]), "r"(a[2]), "r"(a[3]), "r"(b[0]), "r"(b[1]));
}

__global__ void __launch_bounds__(256, 2) gemm6()
{
    extern __shared__ __nv_bfloat16 smem[];
    uint32_t sb;
    asm("{ .reg .u64 t; cvta.to.shared.u64 t, %1; cvt.u32.u64 %0, t; }"
        : "=r"(sb) : "l"(smem));

    const int tid  = threadIdx.x;
    const int lane = tid & 31, wid = tid >> 5;
    const int wm = wid >> 2, wn = wid & 3;          // 2 x 4 warps

    const int g  = blockIdx.z;
    const int bm = blockIdx.y * 128;
    const int bn = blockIdx.x * 128;
    const int arow = ((g & 1) << 12) + bm;
    const int wrow = (g << 10) + bn;

    const __nv_bfloat16* gb[4] = {
        g_Ahi + (size_t)arow * KDIM, g_Alo + (size_t)arow * KDIM,
        g_Whi + (size_t)wrow * KDIM, g_Wlo + (size_t)wrow * KDIM};

    int l_mat[8], l_row[8], l_ch[8];
#pragma unroll
    for (int i = 0; i < 8; i++) {
        const int idx = tid + i * 256;
        l_mat[i] = idx >> 9;
        const int wi = idx & 511;
        l_row[i] = wi >> 2;
        l_ch[i]  = wi & 3;
    }

#define LOAD_STAGE(kt, s)                                                      \
    do {                                                                       \
        const uint32_t sbase_ = sb + (uint32_t)(s) * (STAGE_ELEMS * 2);        \
        _Pragma("unroll")                                                      \
        for (int i = 0; i < 8; i++) {                                          \
            const uint32_t dst = sbase_ +                                      \
                (uint32_t)(l_mat[i] * MAT_ELEMS + l_row[i] * SSTRIDE +         \
                           l_ch[i] * 8) * 2;                                   \
            cp16(dst, gb[l_mat[i]] + (size_t)l_row[i] * KDIM +                 \
                      (kt) * 32 + l_ch[i] * 8);                                \
        }                                                                      \
    } while (0)

    float acc[4][4][4];
#pragma unroll
    for (int mt = 0; mt < 4; mt++)
#pragma unroll
        for (int nt = 0; nt < 4; nt++)
#pragma unroll
            for (int j = 0; j < 4; j++) acc[mt][nt][j] = 0.f;

    LOAD_STAGE(0, 0); CP_COMMIT();
    LOAD_STAGE(1, 1); CP_COMMIT();

    const int a_r = (lane & 7) + ((lane >> 3) & 1) * 8;
    const int a_c = (lane >> 4) * 8;
    const int b_r = (lane & 7) + (lane >> 4) * 8;
    const int b_c = ((lane >> 3) & 1) * 8;

    for (int kt = 0; kt < 32; kt++) {
        CP_WAIT(1);                       // stage kt resident
        __syncthreads();

        const uint32_t sbase = sb + (uint32_t)(kt & 1) * (STAGE_ELEMS * 2);
#pragma unroll
        for (int ks = 0; ks < 2; ks++) {
            uint32_t a[4][4], bq[4][2], tb[4][2];
            // A_hi + B_hi
#pragma unroll
            for (int mt = 0; mt < 4; mt++)
                ldsm4(a[mt], sbase +
                      (uint32_t)((wm * 64 + mt * 16 + a_r) * SSTRIDE +
                                 ks * 16 + a_c) * 2);
#pragma unroll
            for (int p = 0; p < 2; p++) {
                uint32_t q[4];
                ldsm4(q, sbase + (uint32_t)(2 * MAT_ELEMS +
                        (wn * 32 + p * 16 + b_r) * SSTRIDE + ks * 16 + b_c) * 2);
                bq[2 * p][0] = q[0]; bq[2 * p][1] = q[1];
                bq[2 * p + 1][0] = q[2]; bq[2 * p + 1][1] = q[3];
            }
#pragma unroll
            for (int mt = 0; mt < 4; mt++)
#pragma unroll
                for (int nt = 0; nt < 4; nt++)
                    mma16816(acc[mt][nt], a[mt], bq[nt]);
            // B_lo (A_hi reused)
#pragma unroll
            for (int p = 0; p < 2; p++) {
                uint32_t q[4];
                ldsm4(q, sbase + (uint32_t)(3 * MAT_ELEMS +
                        (wn * 32 + p * 16 + b_r) * SSTRIDE + ks * 16 + b_c) * 2);
                tb[2 * p][0] = q[0]; tb[2 * p][1] = q[1];
                tb[2 * p + 1][0] = q[2]; tb[2 * p + 1][1] = q[3];
            }
#pragma unroll
            for (int mt = 0; mt < 4; mt++)
#pragma unroll
                for (int nt = 0; nt < 4; nt++)
                    mma16816(acc[mt][nt], a[mt], tb[nt]);
            // A_lo (B_hi reused), overwrite a[]
#pragma unroll
            for (int mt = 0; mt < 4; mt++)
                ldsm4(a[mt], sbase +
                      (uint32_t)(MAT_ELEMS +
                                 (wm * 64 + mt * 16 + a_r) * SSTRIDE +
                                 ks * 16 + a_c) * 2);
#pragma unroll
            for (int mt = 0; mt < 4; mt++)
#pragma unroll
                for (int nt = 0; nt < 4; nt++)
                    mma16816(acc[mt][nt], a[mt], bq[nt]);
        }

        __syncthreads();                  // everyone done reading stage kt
        if (kt + 2 < 32) LOAD_STAGE(kt + 2, kt & 1);
        CP_COMMIT();
    }
    CP_WAIT(0);

    float* Cb = g_C + (size_t)g * GSZ;
    const int mrow = bm + wm * 64 + (lane >> 2);
    const int ncol = bn + wn * 32 + (lane & 3) * 2;
#pragma unroll
    for (int mt = 0; mt < 4; mt++) {
#pragma unroll
        for (int nt = 0; nt < 4; nt++) {
            float* p0 = Cb + (size_t)(mrow + mt * 16) * NDIM + ncol + nt * 8;
            *reinterpret_cast<float2*>(p0) =
                make_float2(acc[mt][nt][0], acc[mt][nt][1]);
            *reinterpret_cast<float2*>(p0 + 8 * NDIM) =
                make_float2(acc[mt][nt][2], acc[mt][nt][3]);
        }
    }
#undef LOAD_STAGE
}

// ----------------------------------------------------------------------------
// Fused hyperbolic GRU math — fast scalar tails
// ----------------------------------------------------------------------------
#define RT 256
#define VPT 4

struct Vec { float v[VPT]; };

// artanh with reference clip; __logf (lg2.approx) rel-err ~1e-6 in our range
__device__ __forceinline__ float artanh_c(float x)
{
    x = fminf(fmaxf(x, -1.f + 1e-5f), 1.f - 1e-5f);
    return 0.5f * __logf(__fdividef(1.f + x, 1.f - x));
}

// tanh for v >= 0 (our args are products of norms >= 0): 1 - 2/(e^{2v}+1)
__device__ __forceinline__ float tanh_pos(float v)
{
    return 1.f - __fdividef(2.f, __expf(2.f * v) + 1.f);
}

__device__ __forceinline__ float sigmoid_f(float v)
{
    return __fdividef(1.f, 1.f + __expf(-v));
}

__device__ __forceinline__ float blockSum1(float v, float* sbuf)
{
    const int lane = threadIdx.x & 31, wid = threadIdx.x >> 5;
#pragma unroll
    for (int o = 16; o; o >>= 1) v += __shfl_xor_sync(0xffffffffu, v, o);
    __syncthreads();
    if (lane == 0) sbuf[wid] = v;
    __syncthreads();
    float s = 0.f;
#pragma unroll
    for (int i = 0; i < 8; i++) s += sbuf[i];
    return s;
}

__device__ __forceinline__ void blockSum2(float a, float b,
                                          float* ra, float* rb, float* sbuf)
{
    const int lane = threadIdx.x & 31, wid = threadIdx.x >> 5;
#pragma unroll
    for (int o = 16; o; o >>= 1) {
        a += __shfl_xor_sync(0xffffffffu, a, o);
        b += __shfl_xor_sync(0xffffffffu, b, o);
    }
    __syncthreads();
    if (lane == 0) { sbuf[wid] = a; sbuf[8 + wid] = b; }
    __syncthreads();
    float sa = 0.f, sb = 0.f;
#pragma unroll
    for (int i = 0; i < 8; i++) { sa += sbuf[i]; sb += sbuf[8 + i]; }
    *ra = sa; *rb = sb;
}

__device__ __forceinline__ void blockSum3(float a, float b, float c,
                                          float* ra, float* rb, float* rc,
                                          float* sbuf)
{
    const int lane = threadIdx.x & 31, wid = threadIdx.x >> 5;
#pragma unroll
    for (int o = 16; o; o >>= 1) {
        a += __shfl_xor_sync(0xffffffffu, a, o);
        b += __shfl_xor_sync(0xffffffffu, b, o);
        c += __shfl_xor_sync(0xffffffffu, c, o);
    }
    __syncthreads();
    if (lane == 0) { sbuf[wid] = a; sbuf[8 + wid] = b; sbuf[16 + wid] = c; }
    __syncthreads();
    float sa = 0.f, sb = 0.f, sc = 0.f;
#pragma unroll
    for (int i = 0; i < 8; i++) {
        sa += sbuf[i]; sb += sbuf[8 + i]; sc += sbuf[16 + i];
    }
    *ra = sa; *rb = sb; *rc = sc;
}

__device__ __forceinline__ void loadVec(Vec& o, const float* p, int tid)
{
#pragma unroll
    for (int j = 0; j < VPT; j++) o.v[j] = p[j * RT + tid];
}

// mobius_matvec tail: m = tanh(||G|| * inv_xn * atx) * G / ||G||
__device__ __forceinline__ void matvecOp(Vec& m, const float* __restrict__ Grow,
                                         float inv_xn, float atx,
                                         float* sbuf, int tid)
{
    float s = 0.f;
#pragma unroll
    for (int j = 0; j < VPT; j++) {
        float g = Grow[j * RT + tid];
        m.v[j] = g;
        s = fmaf(g, g, s);
    }
    const float g2 = blockSum1(s, sbuf);
    const float inv_gn = rsqrtf(fmaxf(g2, 1e-15f));
    const float gn = g2 * inv_gn;
    const float t = tanh_pos(gn * inv_xn * atx) * inv_gn;
#pragma unroll
    for (int j = 0; j < VPT; j++) m.v[j] *= t;
}

__device__ __forceinline__ void maddOp(Vec& o, const Vec& a, const Vec& b,
                                       float* sbuf)
{
    float sab = 0.f, sa = 0.f, sb = 0.f;
#pragma unroll
    for (int j = 0; j < VPT; j++) {
        sab = fmaf(a.v[j], b.v[j], sab);
        sa  = fmaf(a.v[j], a.v[j], sa);
        sb  = fmaf(b.v[j], b.v[j], sb);
    }
    float ab, a2, b2;
    blockSum3(sab, sa, sb, &ab, &a2, &b2, sbuf);
    const float ca  = 1.f + 2.f * ab + b2;
    const float cb  = 1.f - a2;
    const float den = 1.f + 2.f * ab + a2 * b2;
    const float inv = __fdividef(1.f, den);
#pragma unroll
    for (int j = 0; j < VPT; j++)
        o.v[j] = (ca * a.v[j] + cb * b.v[j]) * inv;
}

__device__ __forceinline__ void pprodOp(Vec& o, const Vec& x, const Vec& u,
                                        float* sbuf)
{
    float ux[VPT];
    float sx = 0.f, su = 0.f;
#pragma unroll
    for (int j = 0; j < VPT; j++) {
        ux[j] = u.v[j] * x.v[j];
        sx = fmaf(x.v[j], x.v[j], sx);
        su = fmaf(ux[j], ux[j], su);
    }
    float x2, ux2;
    blockSum2(sx, su, &x2, &ux2, sbuf);
    const float inv_xn  = rsqrtf(fmaxf(x2, 1e-15f));
    const float xn      = x2 * inv_xn;
    const float inv_uxn = rsqrtf(fmaxf(ux2, 1e-15f));
    const float uxn     = ux2 * inv_uxn;
    const float t = tanh_pos(uxn * inv_xn * artanh_c(xn)) * inv_uxn;
#pragma unroll
    for (int j = 0; j < VPT; j++) o.v[j] = t * ux[j];
}

__device__ __forceinline__ void siglog0Op(Vec& o, const Vec& a, float* sbuf)
{
    float s = 0.f;
#pragma unroll
    for (int j = 0; j < VPT; j++) s = fmaf(a.v[j], a.v[j], s);
    const float n2 = blockSum1(s, sbuf);
    const float inv_n = rsqrtf(fmaxf(n2, 1e-15f));
    const float n = n2 * inv_n;
    const float f = artanh_c(n) * inv_n;
#pragma unroll
    for (int j = 0; j < VPT; j++) o.v[j] = sigmoid_f(f * a.v[j]);
}

__global__ void __launch_bounds__(256) hyp_fused(
    const float* __restrict__ inp, const float* __restrict__ prevh,
    const float* __restrict__ bz, const float* __restrict__ br,
    const float* __restrict__ bh, float* __restrict__ out)
{
    __shared__ float sbuf[24];
    const int row = blockIdx.x;
    const int tid = threadIdx.x;
    const size_t off = (size_t)row * NDIM;
    const float* G = g_C;

    Vec h;
    float sx = 0.f, sh = 0.f;
#pragma unroll
    for (int j = 0; j < VPT; j++) {
        float xv = inp[off + j * RT + tid];
        h.v[j] = prevh[off + j * RT + tid];
        sx = fmaf(xv, xv, sx);
        sh = fmaf(h.v[j], h.v[j], sh);
    }
    float x2, h2;
    blockSum2(sx, sh, &x2, &h2, sbuf);
    const float inv_xn = rsqrtf(fmaxf(x2, 1e-15f));
    const float xn = x2 * inv_xn;
    const float inv_hn = rsqrtf(fmaxf(h2, 1e-15f));
    const float hn = h2 * inv_hn;
    const float atx = artanh_c(xn);     // reused across 3 inp matvecs
    const float ath = artanh_c(hn);     // reused across 3 hid matvecs

    Vec a, b, bias, z, r;

    matvecOp(a, G + 0 * GSZ + off, inv_xn, atx, sbuf, tid);
    matvecOp(b, G + 1 * GSZ + off, inv_hn, ath, sbuf, tid);
    loadVec(bias, bz, tid);
    maddOp(b, b, bias, sbuf);
    maddOp(a, a, b, sbuf);
    siglog0Op(z, a, sbuf);

    matvecOp(a, G + 2 * GSZ + off, inv_xn, atx, sbuf, tid);
    matvecOp(b, G + 3 * GSZ + off, inv_hn, ath, sbuf, tid);
    loadVec(bias, br, tid);
    maddOp(b, b, bias, sbuf);
    maddOp(a, a, b, sbuf);
    siglog0Op(r, a, sbuf);

    matvecOp(a, G + 5 * GSZ + off, inv_hn, ath, sbuf, tid);
    loadVec(bias, bh, tid);
    maddOp(a, a, bias, sbuf);
    pprodOp(a, a, r, sbuf);
    matvecOp(b, G + 4 * GSZ + off, inv_xn, atx, sbuf, tid);
    maddOp(a, a, b, sbuf);
    Vec nh;
#pragma unroll
    for (int j = 0; j < VPT; j++) nh.v[j] = -h.v[j];
    maddOp(a, nh, a, sbuf);
    pprodOp(a, a, z, sbuf);
    maddOp(a, h, a, sbuf);

#pragma unroll
    for (int j = 0; j < VPT; j++) out[off + j * RT + tid] = a.v[j];
}

// ----------------------------------------------------------------------------
// launch
// ----------------------------------------------------------------------------
extern "C" void kernel_launch(void* const* d_in, const int* in_sizes, int n_in,
                              void* d_out, int out_size)
{
    const float* inp   = (const float*)d_in[0];
    const float* prevh = (const float*)d_in[1];
    WPtrs wp;
    wp.w[0] = (const float*)d_in[2];  // w_inp_z
    wp.w[1] = (const float*)d_in[3];  // w_hid_z
    wp.w[2] = (const float*)d_in[5];  // w_inp_r
    wp.w[3] = (const float*)d_in[6];  // w_hid_r
    wp.w[4] = (const float*)d_in[8];  // w_inp_h
    wp.w[5] = (const float*)d_in[9];  // w_hid_h
    const float* b_z = (const float*)d_in[4];
    const float* b_r = (const float*)d_in[7];
    const float* b_h = (const float*)d_in[10];
    float* out = (float*)d_out;

    cudaFuncSetAttribute(gemm6, cudaFuncAttributeMaxDynamicSharedMemorySize,
                         SMEM_BYTES);

    split_act<<<8192, 256>>>(inp, prevh);
    split_wt<<<dim3(32, 32, 6), 256>>>(wp);
    gemm6<<<dim3(8, 32, 6), 256, SMEM_BYTES>>>();
    hyp_fused<<<MDIM, 256>>>(inp, prevh, b_z, b_r, b_h, out);
}

// round 7
// speedup vs baseline: 3.0256x; 1.0226x over previous
#include <cuda_runtime.h>
#include <cuda_bf16.h>
#include <cstdint>

// ============================================================================
// HyperGRUCell — round 7 (= round 6 resubmitted; broker infra failure)
//   split_act : fp32 -> bf16 hi/lo for [inp; prev_h]           (K-major)
//   split_wt  : fp32 W[k][n] -> bf16 hi/lo Wt[n][k] (transpose, K-major)
//   gemm6     : C = Ahi@Whi^T + Ahi@Wlo^T + Alo@Whi^T  (fp32 accum, HMMA)
//   hyp_fused : 2 fused reduction passes via Gram-matrix algebra
// ============================================================================

#define MDIM 4096
#define NDIM 1024
#define KDIM 1024
#define GSZ  ((size_t)MDIM * NDIM)

__device__ float         g_C[6ull * MDIM * NDIM];
__device__ __nv_bfloat16 g_Ahi[8192ull * 1024];
__device__ __nv_bfloat16 g_Alo[8192ull * 1024];
__device__ __nv_bfloat16 g_Whi[6144ull * 1024];
__device__ __nv_bfloat16 g_Wlo[6144ull * 1024];

// ----------------------------------------------------------------------------
// split kernels (unchanged)
// ----------------------------------------------------------------------------
__global__ void __launch_bounds__(256) split_act(const float* __restrict__ inp,
                                                 const float* __restrict__ prevh)
{
    const size_t i = ((size_t)blockIdx.x * 256 + threadIdx.x) * 4;
    const size_t half = (size_t)MDIM * KDIM;
    const float* src = (i < half) ? (inp + i) : (prevh + (i - half));
    float4 v = *reinterpret_cast<const float4*>(src);
    float x[4] = {v.x, v.y, v.z, v.w};
    uint32_t hp[2], lp[2];
#pragma unroll
    for (int j = 0; j < 2; j++) {
        __nv_bfloat16 h0 = __float2bfloat16_rn(x[2 * j]);
        __nv_bfloat16 h1 = __float2bfloat16_rn(x[2 * j + 1]);
        __nv_bfloat16 l0 = __float2bfloat16_rn(x[2 * j] - __bfloat162float(h0));
        __nv_bfloat16 l1 = __float2bfloat16_rn(x[2 * j + 1] - __bfloat162float(h1));
        hp[j] = (uint32_t)__bfloat16_as_ushort(h0) |
                ((uint32_t)__bfloat16_as_ushort(h1) << 16);
        lp[j] = (uint32_t)__bfloat16_as_ushort(l0) |
                ((uint32_t)__bfloat16_as_ushort(l1) << 16);
    }
    *reinterpret_cast<uint2*>(reinterpret_cast<char*>(g_Ahi) + i * 2) = make_uint2(hp[0], hp[1]);
    *reinterpret_cast<uint2*>(reinterpret_cast<char*>(g_Alo) + i * 2) = make_uint2(lp[0], lp[1]);
}

struct WPtrs { const float* w[6]; };

__global__ void __launch_bounds__(256) split_wt(WPtrs wp)
{
    __shared__ float t[32][33];
    const int g = blockIdx.z;
    const float* __restrict__ W = wp.w[g];
    const int tx = threadIdx.x & 31, ty = threadIdx.x >> 5;
    const int n0 = blockIdx.x * 32, k0 = blockIdx.y * 32;
#pragma unroll
    for (int j = 0; j < 4; j++)
        t[ty + j * 8][tx] = W[(size_t)(k0 + ty + j * 8) * NDIM + n0 + tx];
    __syncthreads();
#pragma unroll
    for (int j = 0; j < 4; j++) {
        const float v = t[tx][ty + j * 8];
        __nv_bfloat16 h = __float2bfloat16_rn(v);
        __nv_bfloat16 l = __float2bfloat16_rn(v - __bfloat162float(h));
        const size_t o = (size_t)(g * 1024 + n0 + ty + j * 8) * KDIM + k0 + tx;
        g_Whi[o] = h;
        g_Wlo[o] = l;
    }
}

// ----------------------------------------------------------------------------
// gemm6 (unchanged from round 5 — at legacy HMMA floor)
// ----------------------------------------------------------------------------
#define SSTRIDE 40
#define MAT_ELEMS (128 * SSTRIDE)
#define STAGE_ELEMS (4 * MAT_ELEMS)
#define NSTAGE 2
#define SMEM_BYTES (NSTAGE * STAGE_ELEMS * 2)

__device__ __forceinline__ void cp16(uint32_t dst, const void* src)
{
    asm volatile("cp.async.cg.shared.global [%0], [%1], 16;"
                 :: "r"(dst), "l"(src) : "memory");
}
#define CP_COMMIT() asm volatile("cp.async.commit_group;" ::: "memory")
#define CP_WAIT(n)  asm volatile("cp.async.wait_group %0;" :: "n"(n) : "memory")

__device__ __forceinline__ void ldsm4(uint32_t* d, uint32_t addr)
{
    asm volatile("ldmatrix.sync.aligned.m8n8.x4.shared.b16 {%0,%1,%2,%3}, [%4];"
                 : "=r"(d[0]), "=r"(d[1]), "=r"(d[2]), "=r"(d[3]) : "r"(addr));
}

__device__ __forceinline__ void mma16816(float* c, const uint32_t* a,
                                         const uint32_t* b)
{
    asm volatile(
        "mma.sync.aligned.m16n8k16.row.col.f32.bf16.bf16.f32 "
        "{%0,%1,%2,%3}, {%4,%5,%6,%7}, {%8,%9}, {%0,%1,%2,%3};"
        : "+f"(c[0]), "+f"(c[1]), "+f"(c[2]), "+f"(c[3])
        : "r"(a[0]), "r"(a[1]), "r"(a[2]), "r"(a[3]), "r"(b[0]), "r"(b[1]));
}

__global__ void __launch_bounds__(256, 2) gemm6()
{
    extern __shared__ __nv_bfloat16 smem[];
    uint32_t sb;
    asm("{ .reg .u64 t; cvta.to.shared.u64 t, %1; cvt.u32.u64 %0, t; }"
        : "=r"(sb) : "l"(smem));

    const int tid  = threadIdx.x;
    const int lane = tid & 31, wid = tid >> 5;
    const int wm = wid >> 2, wn = wid & 3;

    const int g  = blockIdx.z;
    const int bm = blockIdx.y * 128;
    const int bn = blockIdx.x * 128;
    const int arow = ((g & 1) << 12) + bm;
    const int wrow = (g << 10) + bn;

    const __nv_bfloat16* gb[4] = {
        g_Ahi + (size_t)arow * KDIM, g_Alo + (size_t)arow * KDIM,
        g_Whi + (size_t)wrow * KDIM, g_Wlo + (size_t)wrow * KDIM};

    int l_mat[8], l_row[8], l_ch[8];
#pragma unroll
    for (int i = 0; i < 8; i++) {
        const int idx = tid + i * 256;
        l_mat[i] = idx >> 9;
        const int wi = idx & 511;
        l_row[i] = wi >> 2;
        l_ch[i]  = wi & 3;
    }

#define LOAD_STAGE(kt, s)                                                      \
    do {                                                                       \
        const uint32_t sbase_ = sb + (uint32_t)(s) * (STAGE_ELEMS * 2);        \
        _Pragma("unroll")                                                      \
        for (int i = 0; i < 8; i++) {                                          \
            const uint32_t dst = sbase_ +                                      \
                (uint32_t)(l_mat[i] * MAT_ELEMS + l_row[i] * SSTRIDE +         \
                           l_ch[i] * 8) * 2;                                   \
            cp16(dst, gb[l_mat[i]] + (size_t)l_row[i] * KDIM +                 \
                      (kt) * 32 + l_ch[i] * 8);                                \
        }                                                                      \
    } while (0)

    float acc[4][4][4];
#pragma unroll
    for (int mt = 0; mt < 4; mt++)
#pragma unroll
        for (int nt = 0; nt < 4; nt++)
#pragma unroll
            for (int j = 0; j < 4; j++) acc[mt][nt][j] = 0.f;

    LOAD_STAGE(0, 0); CP_COMMIT();
    LOAD_STAGE(1, 1); CP_COMMIT();

    const int a_r = (lane & 7) + ((lane >> 3) & 1) * 8;
    const int a_c = (lane >> 4) * 8;
    const int b_r = (lane & 7) + (lane >> 4) * 8;
    const int b_c = ((lane >> 3) & 1) * 8;

    for (int kt = 0; kt < 32; kt++) {
        CP_WAIT(1);
        __syncthreads();

        const uint32_t sbase = sb + (uint32_t)(kt & 1) * (STAGE_ELEMS * 2);
#pragma unroll
        for (int ks = 0; ks < 2; ks++) {
            uint32_t a[4][4], bq[4][2], tb[4][2];
#pragma unroll
            for (int mt = 0; mt < 4; mt++)
                ldsm4(a[mt], sbase +
                      (uint32_t)((wm * 64 + mt * 16 + a_r) * SSTRIDE +
                                 ks * 16 + a_c) * 2);
#pragma unroll
            for (int p = 0; p < 2; p++) {
                uint32_t q[4];
                ldsm4(q, sbase + (uint32_t)(2 * MAT_ELEMS +
                        (wn * 32 + p * 16 + b_r) * SSTRIDE + ks * 16 + b_c) * 2);
                bq[2 * p][0] = q[0]; bq[2 * p][1] = q[1];
                bq[2 * p + 1][0] = q[2]; bq[2 * p + 1][1] = q[3];
            }
#pragma unroll
            for (int mt = 0; mt < 4; mt++)
#pragma unroll
                for (int nt = 0; nt < 4; nt++)
                    mma16816(acc[mt][nt], a[mt], bq[nt]);
#pragma unroll
            for (int p = 0; p < 2; p++) {
                uint32_t q[4];
                ldsm4(q, sbase + (uint32_t)(3 * MAT_ELEMS +
                        (wn * 32 + p * 16 + b_r) * SSTRIDE + ks * 16 + b_c) * 2);
                tb[2 * p][0] = q[0]; tb[2 * p][1] = q[1];
                tb[2 * p + 1][0] = q[2]; tb[2 * p + 1][1] = q[3];
            }
#pragma unroll
            for (int mt = 0; mt < 4; mt++)
#pragma unroll
                for (int nt = 0; nt < 4; nt++)
                    mma16816(acc[mt][nt], a[mt], tb[nt]);
#pragma unroll
            for (int mt = 0; mt < 4; mt++)
                ldsm4(a[mt], sbase +
                      (uint32_t)(MAT_ELEMS +
                                 (wm * 64 + mt * 16 + a_r) * SSTRIDE +
                                 ks * 16 + a_c) * 2);
#pragma unroll
            for (int mt = 0; mt < 4; mt++)
#pragma unroll
                for (int nt = 0; nt < 4; nt++)
                    mma16816(acc[mt][nt], a[mt], bq[nt]);
        }

        __syncthreads();
        if (kt + 2 < 32) LOAD_STAGE(kt + 2, kt & 1);
        CP_COMMIT();
    }
    CP_WAIT(0);

    float* Cb = g_C + (size_t)g * GSZ;
    const int mrow = bm + wm * 64 + (lane >> 2);
    const int ncol = bn + wn * 32 + (lane & 3) * 2;
#pragma unroll
    for (int mt = 0; mt < 4; mt++) {
#pragma unroll
        for (int nt = 0; nt < 4; nt++) {
            float* p0 = Cb + (size_t)(mrow + mt * 16) * NDIM + ncol + nt * 8;
            *reinterpret_cast<float2*>(p0) =
                make_float2(acc[mt][nt][0], acc[mt][nt][1]);
            *reinterpret_cast<float2*>(p0 + 8 * NDIM) =
                make_float2(acc[mt][nt][2], acc[mt][nt][3]);
        }
    }
#undef LOAD_STAGE
}

// ----------------------------------------------------------------------------
// hyp_fused — 2-pass Gram-matrix formulation
// ----------------------------------------------------------------------------
#define RT 256
#define VPT 4

__device__ __forceinline__ float artanh_c(float x)
{
    x = fminf(fmaxf(x, -1.f + 1e-5f), 1.f - 1e-5f);
    return 0.5f * __logf(__fdividef(1.f + x, 1.f - x));
}

__device__ __forceinline__ float tanh_pos(float v)   // v >= 0
{
    return 1.f - __fdividef(2.f, __expf(2.f * v) + 1.f);
}

__device__ __forceinline__ float sigmoid_f(float v)
{
    return __fdividef(1.f, 1.f + __expf(-v));
}

// safe (inv_norm, norm) from squared value
__device__ __forceinline__ void safe_norm(float v2, float& inv_n, float& n)
{
    const float vc = fmaxf(v2, 1e-15f);
    inv_n = rsqrtf(vc);
    n = vc * inv_n;
}

// mobius_matvec scale factor: tanh(||G||*inv_xn*atx)/||G||
__device__ __forceinline__ float mv_factor(float g2, float inv_xn, float atx)
{
    float inv_gn, gn;
    safe_norm(g2, inv_gn, gn);
    return tanh_pos(gn * inv_xn * atx) * inv_gn;
}

// mobius_add scalar coefficients (already divided by denominator)
__device__ __forceinline__ void madd_coef(float ab, float a2, float b2,
                                          float& cA, float& cB)
{
    const float inv = __fdividef(1.f, 1.f + 2.f * ab + a2 * b2);
    cA = (1.f + 2.f * ab + b2) * inv;
    cB = (1.f - a2) * inv;
}

template <int N>
__device__ __forceinline__ void blockReduceN(float* v, float* buf)
{
    const int lane = threadIdx.x & 31, wid = threadIdx.x >> 5;
#pragma unroll
    for (int o = 16; o; o >>= 1)
#pragma unroll
        for (int i = 0; i < N; i++)
            v[i] += __shfl_xor_sync(0xffffffffu, v[i], o);
    if (lane == 0)
#pragma unroll
        for (int i = 0; i < N; i++) buf[wid * N + i] = v[i];
    __syncthreads();
#pragma unroll
    for (int i = 0; i < N; i++) {
        float s = 0.f;
#pragma unroll
        for (int w = 0; w < 8; w++) s += buf[w * N + i];
        v[i] = s;
    }
}

__global__ void __launch_bounds__(256) hyp_fused(
    const float* __restrict__ inp, const float* __restrict__ prevh,
    const float* __restrict__ bzp, const float* __restrict__ brp,
    const float* __restrict__ bhp, float* __restrict__ out)
{
    __shared__ float buf1[8 * 19];
    __shared__ float buf2[8 * 12];
    const int tid = threadIdx.x;
    const size_t off = (size_t)blockIdx.x * NDIM;

    // ---- load everything up front (full MLP) ----
    float H[VPT], G0[VPT], G1[VPT], G2[VPT], G3[VPT], G4[VPT], G5[VPT];
    float BZ[VPT], BR[VPT], BH[VPT];
    float s[19];
#pragma unroll
    for (int i = 0; i < 19; i++) s[i] = 0.f;

#pragma unroll
    for (int j = 0; j < VPT; j++) {
        const int c = j * RT + tid;
        const float xv = inp[off + c];
        H[j]  = prevh[off + c];
        G0[j] = g_C[0 * GSZ + off + c];
        G1[j] = g_C[1 * GSZ + off + c];
        G2[j] = g_C[2 * GSZ + off + c];
        G3[j] = g_C[3 * GSZ + off + c];
        G4[j] = g_C[4 * GSZ + off + c];
        G5[j] = g_C[5 * GSZ + off + c];
        BZ[j] = bzp[c];
        BR[j] = brp[c];
        BH[j] = bhp[c];
        s[0]  = fmaf(xv, xv, s[0]);            // xx
        s[1]  = fmaf(H[j], H[j], s[1]);        // hh
        s[2]  = fmaf(G0[j], G0[j], s[2]);      // g00
        s[3]  = fmaf(G1[j], G1[j], s[3]);      // g11
        s[4]  = fmaf(G0[j], G1[j], s[4]);      // g01
        s[5]  = fmaf(G0[j], BZ[j], s[5]);      // g0z
        s[6]  = fmaf(G1[j], BZ[j], s[6]);      // g1z
        s[7]  = fmaf(BZ[j], BZ[j], s[7]);      // zz
        s[8]  = fmaf(G2[j], G2[j], s[8]);      // g22
        s[9]  = fmaf(G3[j], G3[j], s[9]);      // g33
        s[10] = fmaf(G2[j], G3[j], s[10]);     // g23
        s[11] = fmaf(G2[j], BR[j], s[11]);     // g2r
        s[12] = fmaf(G3[j], BR[j], s[12]);     // g3r
        s[13] = fmaf(BR[j], BR[j], s[13]);     // rrb
        s[14] = fmaf(G5[j], G5[j], s[14]);     // g55
        s[15] = fmaf(G5[j], BH[j], s[15]);     // g5h
        s[16] = fmaf(BH[j], BH[j], s[16]);     // bhbh
        s[17] = fmaf(G4[j], G4[j], s[17]);     // g44
        s[18] = fmaf(G4[j], H[j], s[18]);      // g4H
    }
    blockReduceN<19>(s, buf1);
    const float xx = s[0], hh = s[1];
    const float g00 = s[2], g11 = s[3], g01 = s[4], g0z = s[5], g1z = s[6], zz = s[7];
    const float g22 = s[8], g33 = s[9], g23 = s[10], g2r = s[11], g3r = s[12], rrb = s[13];
    const float g55 = s[14], g5h = s[15], bhbh = s[16], g44 = s[17], g4H = s[18];

    // ---- pass-1 scalar algebra ----
    float inv_xn, xn, inv_hn, hn;
    safe_norm(xx, inv_xn, xn);
    safe_norm(hh, inv_hn, hn);
    const float atx = artanh_c(xn);
    const float ath = artanh_c(hn);

    const float t0 = mv_factor(g00, inv_xn, atx);
    const float t1 = mv_factor(g11, inv_hn, ath);
    const float t2 = mv_factor(g22, inv_xn, atx);
    const float t3 = mv_factor(g33, inv_hn, ath);
    const float t4 = mv_factor(g44, inv_xn, atx);
    const float t5 = mv_factor(g55, inv_hn, ath);

    // z gate: b = madd(t1*G1, BZ); zhat = madd(t0*G0, b); z = sig(log0(zhat))
    float cA, cB;
    madd_coef(t1 * g1z, t1 * t1 * g11, zz, cA, cB);
    const float u1 = cA * t1, u2 = cB;
    madd_coef(t0 * (u1 * g01 + u2 * g0z), t0 * t0 * g00,
              u1 * u1 * g11 + 2.f * u1 * u2 * g1z + u2 * u2 * zz, cA, cB);
    const float w0 = cA * t0, w1 = cB * u1, w2 = cB * u2;
    {
        const float nz2 = w0 * w0 * g00 + w1 * w1 * g11 + w2 * w2 * zz +
                          2.f * (w0 * w1 * g01 + w0 * w2 * g0z + w1 * w2 * g1z);
        float inv_nz, nz;
        safe_norm(nz2, inv_nz, nz);
        const float fz = artanh_c(nz) * inv_nz;
#pragma unroll
        for (int j = 0; j < VPT; j++)
            G0[j] = sigmoid_f(fz * (w0 * G0[j] + w1 * G1[j] + w2 * BZ[j]));
        // G0 now holds z_vec
    }

    // r gate
    madd_coef(t3 * g3r, t3 * t3 * g33, rrb, cA, cB);
    const float v1 = cA * t3, v2 = cB;
    madd_coef(t2 * (v1 * g23 + v2 * g2r), t2 * t2 * g22,
              v1 * v1 * g33 + 2.f * v1 * v2 * g3r + v2 * v2 * rrb, cA, cB);
    const float y0 = cA * t2, y1 = cB * v1, y2 = cB * v2;
    {
        const float nr2 = y0 * y0 * g22 + y1 * y1 * g33 + y2 * y2 * rrb +
                          2.f * (y0 * y1 * g23 + y0 * y2 * g2r + y1 * y2 * g3r);
        float inv_nr, nr;
        safe_norm(nr2, inv_nr, nr);
        const float fr = artanh_c(nr) * inv_nr;
#pragma unroll
        for (int j = 0; j < VPT; j++)
            G1[j] = sigmoid_f(fr * (y0 * G2[j] + y1 * G3[j] + y2 * BR[j]));
        // G1 now holds r_vec
    }

    // ahh = madd(t5*G5, BH) = d5*G5 + db*BH
    madd_coef(t5 * g5h, t5 * t5 * g55, bhbh, cA, cB);
    const float d5 = cA * t5, db = cB;
    const float ahh2 = d5 * d5 * g55 + 2.f * d5 * db * g5h + db * db * bhbh;

    // ---- pass-2 elementwise prep + partial sums ----
    float q[VPT];
    float s2[12];
#pragma unroll
    for (int i = 0; i < 12; i++) s2[i] = 0.f;
#pragma unroll
    for (int j = 0; j < VPT; j++) {
        q[j] = G1[j] * (d5 * G5[j] + db * BH[j]);
        const float z = G0[j];
        const float zh = z * H[j], zq = z * q[j], zg = z * G4[j];
        s2[0]  = fmaf(q[j], q[j], s2[0]);     // qq
        s2[1]  = fmaf(q[j], G4[j], s2[1]);    // qg4
        s2[2]  = fmaf(q[j], H[j], s2[2]);     // qh
        s2[3]  = fmaf(zh, zh, s2[3]);         // s11
        s2[4]  = fmaf(zh, zq, s2[4]);         // s12
        s2[5]  = fmaf(zh, zg, s2[5]);         // s13
        s2[6]  = fmaf(zq, zq, s2[6]);         // s22
        s2[7]  = fmaf(zq, zg, s2[7]);         // s23
        s2[8]  = fmaf(zg, zg, s2[8]);         // s33
        s2[9]  = fmaf(H[j], zh, s2[9]);       // hzh
        s2[10] = fmaf(H[j], zq, s2[10]);      // hzq
        s2[11] = fmaf(H[j], zg, s2[11]);      // hzg4
    }
    blockReduceN<12>(s2, buf2);
    const float qq = s2[0], qg4 = s2[1], qh = s2[2];
    const float s11 = s2[3], s12 = s2[4], s13 = s2[5];
    const float s22 = s2[6], s23 = s2[7], s33 = s2[8];
    const float hzh = s2[9], hzq = s2[10], hzg4 = s2[11];

    // ---- pass-2 scalar algebra ----
    float inv_na, na, inv_nq, nq;
    safe_norm(ahh2, inv_na, na);
    safe_norm(qq, inv_nq, nq);
    const float tp = tanh_pos(nq * inv_na * artanh_c(na)) * inv_nq;

    // temp = madd(p, t4*G4) = bq*q + b4*G4
    madd_coef(tp * t4 * qg4, tp * tp * qq, t4 * t4 * g44, cA, cB);
    const float bq = cA * tp, b4 = cB * t4;

    // minus_h = madd(-H, temp) = alpha*H + bq2*q + b42*G4
    const float temp2 = bq * bq * qq + 2.f * bq * b4 * qg4 + b4 * b4 * g44;
    madd_coef(-(bq * qh + b4 * g4H), hh, temp2, cA, cB);
    const float alpha = -cA, bq2 = cB * bq, b42 = cB * b4;

    // pp = pprod(minus_h, z) = tz * (alpha*zH + bq2*zq + b42*zG4)
    const float mh2 = alpha * alpha * hh + bq2 * bq2 * qq + b42 * b42 * g44 +
                      2.f * (alpha * bq2 * qh + alpha * b42 * g4H + bq2 * b42 * qg4);
    const float ux2 = alpha * alpha * s11 + bq2 * bq2 * s22 + b42 * b42 * s33 +
                      2.f * (alpha * bq2 * s12 + alpha * b42 * s13 + bq2 * b42 * s23);
    float inv_nmh, nmh, inv_nux, nux;
    safe_norm(mh2, inv_nmh, nmh);
    safe_norm(ux2, inv_nux, nux);
    const float tz = tanh_pos(nux * inv_nmh * artanh_c(nmh)) * inv_nux;

    // out = madd(H, pp)
    madd_coef(tz * (alpha * hzh + bq2 * hzq + b42 * hzg4), hh, tz * tz * ux2,
              cA, cB);
    const float k0 = cA;
    const float kz = cB * tz;
    const float ka = kz * alpha, kb = kz * bq2, kc = kz * b42;

#pragma unroll
    for (int j = 0; j < VPT; j++) {
        const float z = G0[j];
        out[off + j * RT + tid] =
            k0 * H[j] + z * (ka * H[j] + kb * q[j] + kc * G4[j]);
    }
}

// ----------------------------------------------------------------------------
// launch
// ----------------------------------------------------------------------------
extern "C" void kernel_launch(void* const* d_in, const int* in_sizes, int n_in,
                              void* d_out, int out_size)
{
    const float* inp   = (const float*)d_in[0];
    const float* prevh = (const float*)d_in[1];
    WPtrs wp;
    wp.w[0] = (const float*)d_in[2];  // w_inp_z
    wp.w[1] = (const float*)d_in[3];  // w_hid_z
    wp.w[2] = (const float*)d_in[5];  // w_inp_r
    wp.w[3] = (const float*)d_in[6];  // w_hid_r
    wp.w[4] = (const float*)d_in[8];  // w_inp_h
    wp.w[5] = (const float*)d_in[9];  // w_hid_h
    const float* b_z = (const float*)d_in[4];
    const float* b_r = (const float*)d_in[7];
    const float* b_h = (const float*)d_in[10];
    float* out = (float*)d_out;

    cudaFuncSetAttribute(gemm6, cudaFuncAttributeMaxDynamicSharedMemorySize,
                         SMEM_BYTES);

    split_act<<<8192, 256>>>(inp, prevh);
    split_wt<<<dim3(32, 32, 6), 256>>>(wp);
    gemm6<<<dim3(8, 32, 6), 256, SMEM_BYTES>>>();
    hyp_fused<<<MDIM, 256>>>(inp, prevh, b_z, b_r, b_h, out);
}